// round 1
// baseline (speedup 1.0000x reference)
#include <cuda_runtime.h>
#include <math_constants.h>

// Problem constants (B=4, N=M=4096, D=3; scalar fp32 output)
#define BATCH 4
#define NPTS  4096
#define TPB   128          // threads per block (1 query point per thread)
#define TILE  2048         // target points cached per smem tile (32 KB float4)
#define BLKS_PER_DIR (BATCH * (NPTS / TPB))   // 4*32 = 128

// Partial sums: [direction][block]
__device__ float g_partial[2][BLKS_PER_DIR];

__global__ __launch_bounds__(TPB)
void chamfer_min_kernel(const float* __restrict__ X, const float* __restrict__ Y) {
    const int dir = blockIdx.y;                 // 0: x->y, 1: y->x
    const int b   = blockIdx.z;                 // batch
    const float* __restrict__ Q = dir ? Y : X;  // query set
    const float* __restrict__ T = dir ? X : Y;  // target set

    const int qi = blockIdx.x * TPB + threadIdx.x;      // query point index
    const float* qp = Q + ((size_t)b * NPTS + qi) * 3;
    const float q0 = qp[0], q1 = qp[1], q2 = qp[2];
    const float qn = q0 * q0 + q1 * q1 + q2 * q2;       // ||x||^2

    __shared__ float4 sy[TILE];
    __shared__ float wsum[TPB / 32];

    // Independent min accumulators (break FMNMX loop-carried latency chain)
    float m0 = CUDART_INF_F, m1 = CUDART_INF_F, m2 = CUDART_INF_F, m3 = CUDART_INF_F;

    for (int tile = 0; tile < NPTS; tile += TILE) {
        // Cooperative load of target tile: (t0,t1,t2, 0.5*||t||^2)
        for (int j = threadIdx.x; j < TILE; j += TPB) {
            const float* tp = T + ((size_t)b * NPTS + tile + j) * 3;
            const float t0 = tp[0], t1 = tp[1], t2 = tp[2];
            sy[j] = make_float4(t0, t1, t2,
                                0.5f * (t0 * t0 + t1 * t1 + t2 * t2));
        }
        __syncthreads();

        #pragma unroll 2
        for (int j = 0; j < TILE; j += 4) {
            const float4 p0 = sy[j + 0];
            const float4 p1 = sy[j + 1];
            const float4 p2 = sy[j + 2];
            const float4 p3 = sy[j + 3];
            // s = 0.5*||t||^2 - q . t   (3-FMA chain each)
            float s0 = fmaf(-q2, p0.z, p0.w);
            float s1 = fmaf(-q2, p1.z, p1.w);
            float s2 = fmaf(-q2, p2.z, p2.w);
            float s3 = fmaf(-q2, p3.z, p3.w);
            s0 = fmaf(-q1, p0.y, s0);
            s1 = fmaf(-q1, p1.y, s1);
            s2 = fmaf(-q1, p2.y, s2);
            s3 = fmaf(-q1, p3.y, s3);
            s0 = fmaf(-q0, p0.x, s0);
            s1 = fmaf(-q0, p1.x, s1);
            s2 = fmaf(-q0, p2.x, s2);
            s3 = fmaf(-q0, p3.x, s3);
            m0 = fminf(m0, s0);
            m1 = fminf(m1, s1);
            m2 = fminf(m2, s2);
            m3 = fminf(m3, s3);
        }
        __syncthreads();
    }

    const float m = fminf(fminf(m0, m1), fminf(m2, m3));
    // d2_min = max(||q||^2 + 2*min_s, 0)  (clamp commutes with min)
    float d2 = fmaxf(fmaf(2.0f, m, qn), 0.0f);

    // Block-reduce sum of d2 (deterministic)
    #pragma unroll
    for (int o = 16; o > 0; o >>= 1)
        d2 += __shfl_xor_sync(0xFFFFFFFFu, d2, o);
    const int wid  = threadIdx.x >> 5;
    const int lane = threadIdx.x & 31;
    if (lane == 0) wsum[wid] = d2;
    __syncthreads();
    if (threadIdx.x == 0) {
        float s = 0.0f;
        #pragma unroll
        for (int w = 0; w < TPB / 32; w++) s += wsum[w];
        g_partial[dir][b * (NPTS / TPB) + blockIdx.x] = s;
    }
}

__global__ __launch_bounds__(BLKS_PER_DIR)
void chamfer_finalize_kernel(float* __restrict__ out) {
    __shared__ float w0[BLKS_PER_DIR / 32];
    __shared__ float w1[BLKS_PER_DIR / 32];
    float s0 = g_partial[0][threadIdx.x];
    float s1 = g_partial[1][threadIdx.x];
    #pragma unroll
    for (int o = 16; o > 0; o >>= 1) {
        s0 += __shfl_xor_sync(0xFFFFFFFFu, s0, o);
        s1 += __shfl_xor_sync(0xFFFFFFFFu, s1, o);
    }
    const int wid  = threadIdx.x >> 5;
    const int lane = threadIdx.x & 31;
    if (lane == 0) { w0[wid] = s0; w1[wid] = s1; }
    __syncthreads();
    if (threadIdx.x == 0) {
        float a = 0.0f, c = 0.0f;
        #pragma unroll
        for (int w = 0; w < BLKS_PER_DIR / 32; w++) { a += w0[w]; c += w1[w]; }
        out[0] = fmaxf(a, c) * (1.0f / (float)(BATCH * NPTS));
    }
}

extern "C" void kernel_launch(void* const* d_in, const int* in_sizes, int n_in,
                              void* d_out, int out_size) {
    const float* x = (const float*)d_in[0];
    const float* y = (const float*)d_in[1];
    float* out = (float*)d_out;

    dim3 grid(NPTS / TPB, 2, BATCH);   // (32, 2, 4) = 256 blocks
    chamfer_min_kernel<<<grid, TPB>>>(x, y);
    chamfer_finalize_kernel<<<1, BLKS_PER_DIR>>>(out);
}

// round 2
// speedup vs baseline: 1.9151x; 1.9151x over previous
#include <cuda_runtime.h>
#include <math_constants.h>

// B=4, N=M=4096, D=3; scalar fp32 output
#define BATCH   4
#define NPTS    4096
#define TPB     128
#define RQ      4                       // queries per thread
#define QPB     (TPB * RQ)              // 512 queries per block
#define QCHUNKS (NPTS / QPB)            // 8
#define SSPLIT  16                      // target-range splits
#define TILE_T  (NPTS / SSPLIT)         // 256 targets per block
#define NBLOCKS (2 * BATCH * QCHUNKS * SSPLIT)   // 1024
#define NQ_TOT  (2 * BATCH * NPTS)      // 32768 query jobs
#define CBLOCKS 128                     // combine kernel blocks
#define CTPB    256

// Scratch: partial min (of s = 0.5||t||^2 - q.t) per (query-job, split)
__device__ float g_partial[NQ_TOT * SSPLIT];   // 2 MB
__device__ float g_bsum[CBLOCKS];
__device__ unsigned int g_count;               // zero-init, self-resetting

typedef unsigned long long ull;

__device__ __forceinline__ ull pack2(float v) {
    ull r;
    asm("mov.b64 %0, {%1, %1};" : "=l"(r) : "f"(v));
    return r;
}
__device__ __forceinline__ ull fma2(ull a, ull b, ull c) {
    ull d;
    asm("fma.rn.f32x2 %0, %1, %2, %3;" : "=l"(d) : "l"(a), "l"(b), "l"(c));
    return d;
}
__device__ __forceinline__ void min2(float& m0, float& m1, ull s) {
    float lo, hi;
    asm("mov.b64 {%0, %1}, %2;" : "=f"(lo), "=f"(hi) : "l"(s));
    m0 = fminf(m0, lo);
    m1 = fminf(m1, hi);
}

__global__ __launch_bounds__(TPB)
void chamfer_partial_kernel(const float* __restrict__ X, const float* __restrict__ Y) {
    const int bid = blockIdx.x;
    const int s   = bid & (SSPLIT - 1);          // bits 0-3
    const int qc  = (bid >> 4) & (QCHUNKS - 1);  // bits 4-6
    const int b   = (bid >> 7) & (BATCH - 1);    // bits 7-8
    const int dir = bid >> 9;                    // bit 9: 0 x->y, 1 y->x

    const float* __restrict__ Q = dir ? Y : X;
    const float* __restrict__ T = dir ? X : Y;

    __shared__ __align__(16) float sx0[TILE_T];
    __shared__ __align__(16) float sx1[TILE_T];
    __shared__ __align__(16) float sx2[TILE_T];
    __shared__ __align__(16) float swv[TILE_T];

    // Load target tile (SoA): coords + 0.5*||t||^2
    const int tb = s * TILE_T;
    for (int t = threadIdx.x; t < TILE_T; t += TPB) {
        const float* tp = T + ((size_t)b * NPTS + tb + t) * 3;
        const float a0 = tp[0], a1 = tp[1], a2 = tp[2];
        sx0[t] = a0; sx1[t] = a1; sx2[t] = a2;
        swv[t] = 0.5f * (a0 * a0 + a1 * a1 + a2 * a2);
    }

    // Per-thread queries (RQ of them, stride TPB for coalescing)
    const int q0 = qc * QPB + threadIdx.x;
    ull nx[RQ], ny[RQ], nz[RQ];
    #pragma unroll
    for (int r = 0; r < RQ; r++) {
        const int q = q0 + r * TPB;
        const float* qp = Q + ((size_t)b * NPTS + q) * 3;
        const float a = qp[0], c = qp[1], d = qp[2];
        nx[r] = pack2(-a); ny[r] = pack2(-c); nz[r] = pack2(-d);
    }
    __syncthreads();

    float m0[RQ], m1[RQ];
    #pragma unroll
    for (int r = 0; r < RQ; r++) { m0[r] = CUDART_INF_F; m1[r] = CUDART_INF_F; }

    const ulonglong2* px = (const ulonglong2*)sx0;
    const ulonglong2* py = (const ulonglong2*)sx1;
    const ulonglong2* pz = (const ulonglong2*)sx2;
    const ulonglong2* pw = (const ulonglong2*)swv;

    #pragma unroll 2
    for (int g = 0; g < TILE_T / 4; g++) {
        const ulonglong2 Xv = px[g];
        const ulonglong2 Yv = py[g];
        const ulonglong2 Zv = pz[g];
        const ulonglong2 Wv = pw[g];
        #pragma unroll
        for (int r = 0; r < RQ; r++) {
            // s = 0.5||t||^2 - q.t  (packed over 2 targets each)
            const ull s01 = fma2(nx[r], Xv.x, fma2(ny[r], Yv.x, fma2(nz[r], Zv.x, Wv.x)));
            const ull s23 = fma2(nx[r], Xv.y, fma2(ny[r], Yv.y, fma2(nz[r], Zv.y, Wv.y)));
            min2(m0[r], m1[r], s01);
            min2(m0[r], m1[r], s23);
        }
    }

    // Store partial min of s for each query job
    #pragma unroll
    for (int r = 0; r < RQ; r++) {
        const int q = q0 + r * TPB;
        const size_t item = ((size_t)(dir * BATCH + b) * NPTS + q);
        g_partial[item * SSPLIT + s] = fminf(m0[r], m1[r]);
    }
}

__global__ __launch_bounds__(CTPB)
void chamfer_combine_kernel(const float* __restrict__ X, const float* __restrict__ Y,
                            float* __restrict__ out) {
    const int item = blockIdx.x * CTPB + threadIdx.x;   // 0..32767, block = single dir
    const int dir  = item >> 14;
    const int rem  = item & 16383;
    const int b    = rem >> 12;
    const int q    = rem & 4095;

    const float* __restrict__ Q = dir ? Y : X;
    const float* qp = Q + ((size_t)b * NPTS + q) * 3;
    const float a = qp[0], c = qp[1], d = qp[2];
    const float qn = a * a + c * c + d * d;

    const float4* pr = (const float4*)(g_partial + (size_t)item * SSPLIT);
    float m = CUDART_INF_F;
    #pragma unroll
    for (int k = 0; k < SSPLIT / 4; k++) {
        const float4 v = pr[k];
        m = fminf(m, fminf(fminf(v.x, v.y), fminf(v.z, v.w)));
    }
    float d2 = fmaxf(fmaf(2.0f, m, qn), 0.0f);

    // Block sum (deterministic)
    __shared__ float wsum[CTPB / 32];
    #pragma unroll
    for (int o = 16; o > 0; o >>= 1)
        d2 += __shfl_xor_sync(0xFFFFFFFFu, d2, o);
    const int wid  = threadIdx.x >> 5;
    const int lane = threadIdx.x & 31;
    if (lane == 0) wsum[wid] = d2;
    __syncthreads();

    __shared__ unsigned int ticket;
    if (threadIdx.x == 0) {
        float ssum = 0.0f;
        #pragma unroll
        for (int w = 0; w < CTPB / 32; w++) ssum += wsum[w];
        g_bsum[blockIdx.x] = ssum;
        __threadfence();
        ticket = atomicAdd(&g_count, 1u);
    }
    __syncthreads();

    if (ticket == CBLOCKS - 1) {
        // Last block finalizes: blocks [0,64) are dir0, [64,128) dir1
        if (threadIdx.x == 0) {
            float s0 = 0.0f, s1 = 0.0f;
            for (int i = 0; i < CBLOCKS / 2; i++)      s0 += __ldcg(&g_bsum[i]);
            for (int i = CBLOCKS / 2; i < CBLOCKS; i++) s1 += __ldcg(&g_bsum[i]);
            out[0] = fmaxf(s0, s1) * (1.0f / (float)(BATCH * NPTS));
            g_count = 0;   // reset for graph replay
        }
    }
}

extern "C" void kernel_launch(void* const* d_in, const int* in_sizes, int n_in,
                              void* d_out, int out_size) {
    const float* x = (const float*)d_in[0];
    const float* y = (const float*)d_in[1];
    float* out = (float*)d_out;

    chamfer_partial_kernel<<<NBLOCKS, TPB>>>(x, y);
    chamfer_combine_kernel<<<CBLOCKS, CTPB>>>(x, y, out);
}